// round 13
// baseline (speedup 1.0000x reference)
#include <cuda_runtime.h>
#include <cuda_fp16.h>
#include <math.h>
#include <stdint.h>

#define NB 64
#define NC 64
#define NH 56
#define NW 56
#define HW 3136
#define CHW 200704
#define OUT_MAIN (NB*CHW)

__device__ int   g_eidx[NB*2];
__device__ float g_ewt[NB*2];
__device__ float g_pooled[NB*NC];
__device__ unsigned int g_pcount;
__device__ unsigned int g_zflag[NB];

#define WT      8192
#define SM_W1   0
#define SM_W2   73728
#define SLOT    7424                 // 58 rows x 128B
#define SM_XR   147456               // 4 slots
#define SM_YR   177152               // 7 slots
#define SM_FLAG 229120
#define SM_TOTAL 229136

__device__ __forceinline__ uint32_t smem_u32(const void* p){
    uint32_t a; asm("{ .reg .u64 t; cvta.to.shared.u64 t, %1; cvt.u32.u64 %0, t; }":"=r"(a):"l"(p)); return a;
}
#define LDSM4(d0,d1,d2,d3,a) \
    asm volatile("ldmatrix.sync.aligned.m8n8.x4.shared.b16 {%0,%1,%2,%3},[%4];" \
        : "=r"(d0),"=r"(d1),"=r"(d2),"=r"(d3) : "r"(a))
#define LDSM2(d0,d1,a) \
    asm volatile("ldmatrix.sync.aligned.m8n8.x2.shared.b16 {%0,%1},[%2];" \
        : "=r"(d0),"=r"(d1) : "r"(a))
#define MMA16816(C,a0,a1,a2,a3,b0,b1) \
    asm volatile("mma.sync.aligned.m16n8k16.row.col.f32.f16.f16.f32 " \
        "{%0,%1,%2,%3},{%4,%5,%6,%7},{%8,%9},{%0,%1,%2,%3};" \
        : "+f"((C)[0]),"+f"((C)[1]),"+f"((C)[2]),"+f"((C)[3]) \
        : "r"(a0),"r"(a1),"r"(a2),"r"(a3),"r"(b0),"r"(b1))

// ---------------------------------------------------------------------------
// Pool (grid 64x8) with gate finalize folded into the last-arriving block.
// ---------------------------------------------------------------------------
__global__ void pool_gate(const float* __restrict__ x, const float* __restrict__ gw,
                          const float* __restrict__ gb, float* __restrict__ dw){
    int b = blockIdx.x, gg = blockIdx.y;
    int w = threadIdx.x>>5, l = threadIdx.x&31;
    int c = gg*8 + w;
    const float4* p = (const float4*)(x + ((size_t)b*NC + c)*HW);
    float s = 0.f;
    for (int i=l; i<HW/4; i+=32){ float4 v = p[i]; s += (v.x+v.y)+(v.z+v.w); }
    #pragma unroll
    for (int o=16;o>0;o>>=1) s += __shfl_xor_sync(0xffffffffu, s, o);
    if (l==0) g_pooled[b*NC+c] = s * (1.0f/(float)HW);
    __threadfence();
    __shared__ int last;
    if (threadIdx.x==0){
        unsigned old = atomicAdd(&g_pcount, 1u);
        last = (((old+1u)&511u)==0u);           // 512 blocks per launch
    }
    __syncthreads();
    if (last && threadIdx.x < NB){
        int bb = threadIdx.x;
        float lg[8];
        #pragma unroll
        for (int e=0;e<8;e++){
            float t = gb[e];
            for (int cc=0;cc<NC;cc++) t += g_pooled[bb*NC+cc]*gw[e*NC+cc];
            lg[e] = t;
        }
        int i0=0; float v0=lg[0];
        #pragma unroll
        for (int e=1;e<8;e++) if (lg[e]>v0){ v0=lg[e]; i0=e; }
        int i1=-1; float v1=-1e30f;
        #pragma unroll
        for (int e=0;e<8;e++){ if (e==i0) continue; if (lg[e]>v1){ v1=lg[e]; i1=e; } }
        float w0 = 1.0f/(1.0f+expf(v1-v0));
        g_eidx[bb*2+0]=i0; g_eidx[bb*2+1]=i1;
        g_ewt [bb*2+0]=w0; g_ewt [bb*2+1]=1.0f-w0;
        if (dw){
            float rowv[8] = {0,0,0,0,0,0,0,0};
            rowv[i0]=w0; rowv[i1]=1.0f-w0;
            #pragma unroll
            for (int e=0;e<8;e++) dw[bb*8+e]=rowv[e];
        }
    }
}

__device__ __forceinline__ void loadx_regs(const float* __restrict__ in, int r,
                                           __half* hb, int tid){
    if (r >= NH) return;
    int ci = tid>>2, q = tid&3;
    const float* src = in + (size_t)ci*HW + r*NW + q*14;
    #pragma unroll
    for (int j=0;j<14;j++) hb[j] = __float2half(src[j]);
}
__device__ __forceinline__ void stsx_regs(char* smem, int r, const __half* hb, int tid){
    if (r >= NH) return;
    int ci = tid>>2, q = tid&3;
    uint32_t base = SM_XR + (uint32_t)(r&3)*SLOT;
    uint32_t cb2 = (uint32_t)(ci*2);
    #pragma unroll
    for (int j=0;j<14;j++){
        uint32_t c = (uint32_t)(q*14 + j + 1);
        *(__half*)(smem + base + c*128 + (cb2 ^ ((c&7)<<4))) = hb[j];
    }
}

// Warp computes M32xN32 for TWO adjacent rows; A frags shared, B rows shared.
template<int WN>
__device__ __forceinline__ void conv_pair(
    uint32_t sbase, uint32_t wOff, const uint32_t dyb[4], uint32_t vmask,
    const uint32_t rAoff[2], const uint32_t sxA[2], uint32_t kbA0,
    uint32_t rb0, uint32_t kbB0, uint32_t lane, float (&C)[2][2][4][4])
{
    #pragma unroll 1
    for (int kx=0; kx<3; kx++){
        #pragma unroll
        for (int ks=0; ks<4; ks++){
            uint32_t kA = kbA0 + (uint32_t)ks*32;
            uint32_t kB = kbB0 + (uint32_t)ks*32;
            uint32_t a[3][2][4];
            #pragma unroll
            for (int ky=0; ky<3; ky++){
                uint32_t aT = sbase + wOff + (uint32_t)(3*ky+kx)*WT;
                #pragma unroll
                for (int mt=0; mt<2; mt++)
                    LDSM4(a[ky][mt][0],a[ky][mt][1],a[ky][mt][2],a[ky][mt][3],
                          aT + rAoff[mt] + (kA ^ sxA[mt]));
            }
            #pragma unroll
            for (int d=0; d<4; d++){
                if (!((vmask>>d)&1u)) continue;
                uint32_t b[8];
                uint32_t rb = rb0 + (uint32_t)kx;
                LDSM4(b[0],b[1],b[2],b[3], dyb[d] + rb*128 + (kB ^ ((rb&7)<<4)));
                if (WN==0){
                    uint32_t rb2 = rb + 16;
                    LDSM4(b[4],b[5],b[6],b[7], dyb[d] + rb2*128 + (kB ^ ((rb2&7)<<4)));
                } else {
                    uint32_t rb2 = 48u + (lane&7) + (uint32_t)kx;
                    uint32_t kk = (uint32_t)ks*32 + ((lane>>3)&1u)*16u;
                    LDSM2(b[4],b[5], dyb[d] + rb2*128 + (kk ^ ((rb2&7)<<4)));
                }
                #pragma unroll
                for (int rr=0; rr<2; rr++){
                    int ky = d - rr;
                    if (ky < 0 || ky > 2) continue;
                    #pragma unroll
                    for (int mt=0; mt<2; mt++){
                        MMA16816(C[rr][mt][0], a[ky][mt][0],a[ky][mt][1],a[ky][mt][2],a[ky][mt][3], b[0],b[1]);
                        MMA16816(C[rr][mt][1], a[ky][mt][0],a[ky][mt][1],a[ky][mt][2],a[ky][mt][3], b[2],b[3]);
                        MMA16816(C[rr][mt][2], a[ky][mt][0],a[ky][mt][1],a[ky][mt][2],a[ky][mt][3], b[4],b[5]);
                        if (WN==0)
                        MMA16816(C[rr][mt][3], a[ky][mt][0],a[ky][mt][1],a[ky][mt][2],a[ky][mt][3], b[6],b[7]);
                    }
                }
            }
        }
    }
}

// Fused BasicBlock per (b,slot). 8 warps = 2cv x 2wm x 2wn, 29 iters.
// it==0: cv1 warps zero this CTA's half of b's output (ticket on g_zflag[b]).
// it<28: cv0 conv1 rows (y,y+1); cv1 conv2 rows (y-4,y-3) for it>=2 (spin at it==2).
// it==28: BOTH run conv2 tail.
__global__ void __launch_bounds__(256,1) fused_block(
    const float* __restrict__ x,
    const float* __restrict__ w1_all, const float* __restrict__ bn1_s, const float* __restrict__ bn1_b,
    const float* __restrict__ w2_all, const float* __restrict__ bn2_s, const float* __restrict__ bn2_b,
    float* __restrict__ out)
{
    extern __shared__ char smem[];
    const int tid = threadIdx.x, wid = tid>>5, lane = tid&31;
    const int cv = wid>>2;
    const int wm = (wid>>1)&1;
    const int wn = (wid&1)^cv;
    const int bs = blockIdx.x, b = bs>>1;
    const int e = g_eidx[bs];
    const float wt = g_ewt[bs];
    const float* in = x + (size_t)b*CHW;
    float* dst = out + (size_t)b*CHW;
    const uint32_t sbase = smem_u32(smem);

    for (int i=tid; i<(SM_YR+7*SLOT-SM_XR)/4; i+=256) ((uint32_t*)(smem+SM_XR))[i] = 0;

    for (int p=tid; p<4096; p+=256){
        int co = p>>6, ci = p&63;
        const float* wp1 = w1_all + (size_t)e*NC*NC*9 + (size_t)p*9;
        const float* wp2 = w2_all + (size_t)e*NC*NC*9 + (size_t)p*9;
        uint32_t off0 = (uint32_t)co*128 + (((uint32_t)(ci*2)) ^ ((uint32_t)(co&7)<<4));
        #pragma unroll
        for (int g9=0; g9<9; g9++){
            *(__half*)(smem + SM_W1 + g9*WT + off0) = __float2half(wp1[g9]);
            *(__half*)(smem + SM_W2 + g9*WT + off0) = __float2half(wp2[g9]);
        }
    }
    __syncthreads();
    {
        __half t[14];
        #pragma unroll
        for (int r=0;r<3;r++){ loadx_regs(in, r, t, tid); stsx_regs(smem, r, t, tid); }
    }

    const int g = lane>>2;
    float s1a[2], b1a[2], s1b[2], b1b[2], s2a[2], b2a[2], s2b[2], b2b[2];
    #pragma unroll
    for (int mt=0; mt<2; mt++){
        int co0 = wm*32 + mt*16 + g;
        s1a[mt]=bn1_s[e*NC+co0];   b1a[mt]=bn1_b[e*NC+co0];
        s1b[mt]=bn1_s[e*NC+co0+8]; b1b[mt]=bn1_b[e*NC+co0+8];
        s2a[mt]=bn2_s[e*NC+co0];   b2a[mt]=bn2_b[e*NC+co0];
        s2b[mt]=bn2_s[e*NC+co0+8]; b2b[mt]=bn2_b[e*NC+co0+8];
    }
    __syncthreads();

    const int sub = lane>>3, r = lane&7;
    uint32_t rAoff[2], sxA[2];
    #pragma unroll
    for (int mt=0; mt<2; mt++){
        uint32_t rowA = (uint32_t)(wm*32 + mt*16 + (sub&1)*8 + r);
        rAoff[mt] = rowA*128;
        sxA[mt]   = (rowA&7)<<4;
    }
    const uint32_t kbA0 = (uint32_t)((sub>>1)*16);
    const uint32_t rb0  = (uint32_t)(wn*32 + (sub>>1)*8 + r);
    const uint32_t kbB0 = (uint32_t)((sub&1)*16);
    const int xq = 2*(lane&3);

    __half hb0[14], hb1[14];
    loadx_regs(in, 3, hb0, tid);
    loadx_regs(in, 4, hb1, tid);

    for (int it=0; it<29; it++){
        const int y = 2*it;
        if (it>0){
            stsx_regs(smem, y+1, hb0, tid);
            stsx_regs(smem, y+2, hb1, tid);
            __syncthreads();
            loadx_regs(in, y+3, hb0, tid);
            loadx_regs(in, y+4, hb1, tid);
        }
        const int role = (it==28) ? 1 : cv;
        const bool act = (it==28) ? true : (cv==0 ? true : (it>=2));
        if (act){
            const int r0 = (it==28) ? (cv==0 ? 54 : 52) : (role==0 ? y : y-4);
            uint32_t dyb[4], vmask = 0;
            #pragma unroll
            for (int d=0; d<4; d++){
                int iy = r0 + d - 1;
                if (iy >= 0 && iy < NH) vmask |= 1u<<d;
                int ic = iy < 0 ? 0 : iy;
                dyb[d] = role==0 ? sbase + SM_XR + (uint32_t)(ic&3)*SLOT
                                 : sbase + SM_YR + (uint32_t)(ic%7)*SLOT;
            }
            float C[2][2][4][4];
            #pragma unroll
            for (int rr=0;rr<2;rr++)
                #pragma unroll
                for (int mt=0;mt<2;mt++)
                    #pragma unroll
                    for (int t=0;t<4;t++){ C[rr][mt][t][0]=0;C[rr][mt][t][1]=0;C[rr][mt][t][2]=0;C[rr][mt][t][3]=0; }

            const uint32_t wOff = role ? SM_W2 : SM_W1;
            if (wn==0) conv_pair<0>(sbase,wOff,dyb,vmask,rAoff,sxA,kbA0,rb0,kbB0,(uint32_t)lane,C);
            else       conv_pair<1>(sbase,wOff,dyb,vmask,rAoff,sxA,kbA0,rb0,kbB0,(uint32_t)lane,C);

            if (role==0){
                #pragma unroll
                for (int rr=0;rr<2;rr++){
                    int yr = r0+rr;
                    char* yb = smem + SM_YR + (uint32_t)(yr%7)*SLOT;
                    #pragma unroll
                    for (int mt=0;mt<2;mt++){
                        int co0 = wm*32 + mt*16 + g, co1 = co0+8;
                        #pragma unroll
                        for (int t=0;t<4;t++){
                            if (wn==1 && t==3) continue;
                            int px = wn*32 + t*8 + xq;
                            float v0 = fmaxf(C[rr][mt][t][0]*s1a[mt] + b1a[mt], 0.f);
                            float v1 = fmaxf(C[rr][mt][t][1]*s1a[mt] + b1a[mt], 0.f);
                            float v2 = fmaxf(C[rr][mt][t][2]*s1b[mt] + b1b[mt], 0.f);
                            float v3 = fmaxf(C[rr][mt][t][3]*s1b[mt] + b1b[mt], 0.f);
                            uint32_t c0 = (uint32_t)(px+1), c1 = (uint32_t)(px+2);
                            uint32_t s0 = (c0&7)<<4, s1 = (c1&7)<<4;
                            *(__half*)(yb + c0*128 + (((uint32_t)(co0*2)) ^ s0)) = __float2half(v0);
                            *(__half*)(yb + c1*128 + (((uint32_t)(co0*2)) ^ s1)) = __float2half(v1);
                            *(__half*)(yb + c0*128 + (((uint32_t)(co1*2)) ^ s0)) = __float2half(v2);
                            *(__half*)(yb + c1*128 + (((uint32_t)(co1*2)) ^ s1)) = __float2half(v3);
                        }
                    }
                }
            } else {
                if (it==2){
                    unsigned tgt = *(volatile unsigned*)(smem+SM_FLAG);
                    while (*(volatile unsigned*)&g_zflag[b] < tgt) {}
                }
                #pragma unroll
                for (int rr=0;rr<2;rr++){
                    int yr = r0+rr;
                    #pragma unroll
                    for (int mt=0;mt<2;mt++){
                        int co0 = wm*32 + mt*16 + g, co1 = co0+8;
                        #pragma unroll
                        for (int t=0;t<4;t++){
                            if (wn==1 && t==3) continue;
                            int px = wn*32 + t*8 + xq;
                            float v0 = C[rr][mt][t][0]*s2a[mt] + b2a[mt];
                            float v1 = C[rr][mt][t][1]*s2a[mt] + b2a[mt];
                            float v2 = C[rr][mt][t][2]*s2b[mt] + b2b[mt];
                            float v3 = C[rr][mt][t][3]*s2b[mt] + b2b[mt];
                            int i0 = co0*HW + yr*NW + px;
                            int i1 = co1*HW + yr*NW + px;
                            float2 r0v = *(const float2*)(in+i0);
                            float2 r1v = *(const float2*)(in+i1);
                            atomicAdd(dst+i0,   wt*fmaxf(v0+r0v.x,0.f));
                            atomicAdd(dst+i0+1, wt*fmaxf(v1+r0v.y,0.f));
                            atomicAdd(dst+i1,   wt*fmaxf(v2+r1v.x,0.f));
                            atomicAdd(dst+i1+1, wt*fmaxf(v3+r1v.y,0.f));
                        }
                    }
                }
            }
        } else if (it==0){
            // cv1 idle slot: zero this CTA's half of b's output, then ticket.
            float4 z4 = make_float4(0.f,0.f,0.f,0.f);
            float4* zp = (float4*)dst + (bs&1)*(CHW/8);
            int t = tid - 128;
            #pragma unroll 1
            for (int i=t; i<CHW/8; i+=128) zp[i] = z4;
            asm volatile("bar.sync 1,128;":::"memory");
            __threadfence();
            if (tid==128){
                unsigned s = atomicAdd(&g_zflag[b], 1u);
                *(volatile unsigned*)(smem+SM_FLAG) = (s & ~1u) + 2u;
            }
            asm volatile("bar.sync 1,128;":::"memory");
        }
        __syncthreads();
    }
}

extern "C" void kernel_launch(void* const* d_in, const int* in_sizes, int n_in,
                              void* d_out, int out_size)
{
    const float* x       = (const float*)d_in[0];
    const float* gate_w  = (const float*)d_in[1];
    const float* gate_b  = (const float*)d_in[2];
    const float* conv1_w = (const float*)d_in[3];
    const float* bn1_s   = (const float*)d_in[4];
    const float* bn1_b   = (const float*)d_in[5];
    const float* conv2_w = (const float*)d_in[6];
    const float* bn2_s   = (const float*)d_in[7];
    const float* bn2_b   = (const float*)d_in[8];
    float* out = (float*)d_out;

    // tail region (dense_w + any extra) zeroed by memset; main region zeroed in-kernel
    if (out_size > OUT_MAIN)
        cudaMemsetAsync(out + OUT_MAIN, 0, (size_t)(out_size - OUT_MAIN)*sizeof(float), 0);

    float* dw = (out_size >= OUT_MAIN + NB*8) ? (out + OUT_MAIN) : nullptr;
    pool_gate<<<dim3(NB,8), 256>>>(x, gate_w, gate_b, dw);

    cudaFuncSetAttribute(fused_block, cudaFuncAttributeMaxDynamicSharedMemorySize, SM_TOTAL);
    fused_block<<<128, 256, SM_TOTAL>>>(x, conv1_w, bn1_s, bn1_b,
                                        conv2_w, bn2_s, bn2_b, out);
}

// round 14
// speedup vs baseline: 1.3137x; 1.3137x over previous
#include <cuda_runtime.h>
#include <cuda_fp16.h>
#include <math.h>
#include <stdint.h>

#define NB 64
#define NC 64
#define NH 56
#define NW 56
#define HW 3136
#define CHW 200704
#define OUT_MAIN (NB*CHW)

__device__ int   g_eidx[NB*2];
__device__ float g_ewt[NB*2];
__device__ float g_pooled[NB*NC];
__device__ unsigned int g_pcount;

#define WT      8192
#define SM_W1   0
#define SM_W2   73728
#define SLOT    7424                 // 58 rows x 128B
#define SM_XR   147456               // 4 slots
#define SM_YR   177152               // 7 slots
#define SM_TOTAL 229120

__device__ __forceinline__ uint32_t smem_u32(const void* p){
    uint32_t a; asm("{ .reg .u64 t; cvta.to.shared.u64 t, %1; cvt.u32.u64 %0, t; }":"=r"(a):"l"(p)); return a;
}
#define LDSM4(d0,d1,d2,d3,a) \
    asm volatile("ldmatrix.sync.aligned.m8n8.x4.shared.b16 {%0,%1,%2,%3},[%4];" \
        : "=r"(d0),"=r"(d1),"=r"(d2),"=r"(d3) : "r"(a))
#define LDSM2(d0,d1,a) \
    asm volatile("ldmatrix.sync.aligned.m8n8.x2.shared.b16 {%0,%1},[%2];" \
        : "=r"(d0),"=r"(d1) : "r"(a))
#define MMA16816(C,a0,a1,a2,a3,b0,b1) \
    asm volatile("mma.sync.aligned.m16n8k16.row.col.f32.f16.f16.f32 " \
        "{%0,%1,%2,%3},{%4,%5,%6,%7},{%8,%9},{%0,%1,%2,%3};" \
        : "+f"((C)[0]),"+f"((C)[1]),"+f"((C)[2]),"+f"((C)[3]) \
        : "r"(a0),"r"(a1),"r"(a2),"r"(a3),"r"(b0),"r"(b1))

// ---------------------------------------------------------------------------
// One launch: pooling blocks (gg<8), zeroing blocks (gg>=8), gate in the
// last-arriving block (epoch counter mod 768; threadfence orders all work).
// ---------------------------------------------------------------------------
__global__ void pool_zero_gate(const float* __restrict__ x, const float* __restrict__ gw,
                               const float* __restrict__ gb, float* __restrict__ out,
                               int out_size){
    int b = blockIdx.x, gg = blockIdx.y;
    if (gg < 8){
        int w = threadIdx.x>>5, l = threadIdx.x&31;
        int c = gg*8 + w;
        const float4* p = (const float4*)(x + ((size_t)b*NC + c)*HW);
        float s = 0.f;
        for (int i=l; i<HW/4; i+=32){ float4 v = p[i]; s += (v.x+v.y)+(v.z+v.w); }
        #pragma unroll
        for (int o=16;o>0;o>>=1) s += __shfl_xor_sync(0xffffffffu, s, o);
        if (l==0) g_pooled[b*NC+c] = s * (1.0f/(float)HW);
    } else {
        // zero main output region: 256 blocks x 256 thr x 49 float4
        int zi = (gg-8)*NB + b;                   // 0..255
        float4 z4 = make_float4(0.f,0.f,0.f,0.f);
        float4* zp = (float4*)out + (size_t)zi*(OUT_MAIN/4/256);
        #pragma unroll 7
        for (int i=(int)threadIdx.x; i<OUT_MAIN/4/256; i+=256) zp[i] = z4;
        if (zi==0){   // tail (dense_w region etc.)
            for (int i=OUT_MAIN+(int)threadIdx.x; i<out_size; i+=256) out[i] = 0.f;
        }
    }
    __threadfence();
    __shared__ int last;
    if (threadIdx.x==0){
        unsigned old = atomicAdd(&g_pcount, 1u);
        last = (((old+1u) % 768u)==0u);
    }
    __syncthreads();
    if (last && threadIdx.x < NB){
        int bb = threadIdx.x;
        float lg[8];
        #pragma unroll
        for (int e=0;e<8;e++){
            float t = gb[e];
            for (int cc=0;cc<NC;cc++) t += g_pooled[bb*NC+cc]*gw[e*NC+cc];
            lg[e] = t;
        }
        int i0=0; float v0=lg[0];
        #pragma unroll
        for (int e=1;e<8;e++) if (lg[e]>v0){ v0=lg[e]; i0=e; }
        int i1=-1; float v1=-1e30f;
        #pragma unroll
        for (int e=0;e<8;e++){ if (e==i0) continue; if (lg[e]>v1){ v1=lg[e]; i1=e; } }
        float w0 = 1.0f/(1.0f+expf(v1-v0));
        g_eidx[bb*2+0]=i0; g_eidx[bb*2+1]=i1;
        g_ewt [bb*2+0]=w0; g_ewt [bb*2+1]=1.0f-w0;
        if (out_size >= OUT_MAIN + NB*8){
            out[OUT_MAIN + bb*8 + i0] = w0;
            out[OUT_MAIN + bb*8 + i1] = 1.0f-w0;
        }
    }
}

__device__ __forceinline__ void loadx_regs(const float* __restrict__ in, int r,
                                           __half* hb, int tid){
    if (r >= NH) return;
    int ci = tid>>2, q = tid&3;
    const float* src = in + (size_t)ci*HW + r*NW + q*14;
    #pragma unroll
    for (int j=0;j<14;j++) hb[j] = __float2half(src[j]);
}
__device__ __forceinline__ void stsx_regs(char* smem, int r, const __half* hb, int tid){
    if (r >= NH) return;
    int ci = tid>>2, q = tid&3;
    uint32_t base = SM_XR + (uint32_t)(r&3)*SLOT;
    uint32_t cb2 = (uint32_t)(ci*2);
    #pragma unroll
    for (int j=0;j<14;j++){
        uint32_t c = (uint32_t)(q*14 + j + 1);
        *(__half*)(smem + base + c*128 + (cb2 ^ ((c&7)<<4))) = hb[j];
    }
}

// Warp computes M32xN32 for TWO adjacent rows; A frags shared, B rows shared.
template<int WN>
__device__ __forceinline__ void conv_pair(
    uint32_t sbase, uint32_t wOff, const uint32_t dyb[4], uint32_t vmask,
    const uint32_t rAoff[2], const uint32_t sxA[2], uint32_t kbA0,
    uint32_t rb0, uint32_t kbB0, uint32_t lane, float (&C)[2][2][4][4])
{
    #pragma unroll 1
    for (int kx=0; kx<3; kx++){
        #pragma unroll
        for (int ks=0; ks<4; ks++){
            uint32_t kA = kbA0 + (uint32_t)ks*32;
            uint32_t kB = kbB0 + (uint32_t)ks*32;
            uint32_t a[3][2][4];
            #pragma unroll
            for (int ky=0; ky<3; ky++){
                uint32_t aT = sbase + wOff + (uint32_t)(3*ky+kx)*WT;
                #pragma unroll
                for (int mt=0; mt<2; mt++)
                    LDSM4(a[ky][mt][0],a[ky][mt][1],a[ky][mt][2],a[ky][mt][3],
                          aT + rAoff[mt] + (kA ^ sxA[mt]));
            }
            #pragma unroll
            for (int d=0; d<4; d++){
                if (!((vmask>>d)&1u)) continue;
                uint32_t b[8];
                uint32_t rb = rb0 + (uint32_t)kx;
                LDSM4(b[0],b[1],b[2],b[3], dyb[d] + rb*128 + (kB ^ ((rb&7)<<4)));
                if (WN==0){
                    uint32_t rb2 = rb + 16;
                    LDSM4(b[4],b[5],b[6],b[7], dyb[d] + rb2*128 + (kB ^ ((rb2&7)<<4)));
                } else {
                    uint32_t rb2 = 48u + (lane&7) + (uint32_t)kx;
                    uint32_t kk = (uint32_t)ks*32 + ((lane>>3)&1u)*16u;
                    LDSM2(b[4],b[5], dyb[d] + rb2*128 + (kk ^ ((rb2&7)<<4)));
                }
                #pragma unroll
                for (int rr=0; rr<2; rr++){
                    int ky = d - rr;
                    if (ky < 0 || ky > 2) continue;
                    #pragma unroll
                    for (int mt=0; mt<2; mt++){
                        MMA16816(C[rr][mt][0], a[ky][mt][0],a[ky][mt][1],a[ky][mt][2],a[ky][mt][3], b[0],b[1]);
                        MMA16816(C[rr][mt][1], a[ky][mt][0],a[ky][mt][1],a[ky][mt][2],a[ky][mt][3], b[2],b[3]);
                        MMA16816(C[rr][mt][2], a[ky][mt][0],a[ky][mt][1],a[ky][mt][2],a[ky][mt][3], b[4],b[5]);
                        if (WN==0)
                        MMA16816(C[rr][mt][3], a[ky][mt][0],a[ky][mt][1],a[ky][mt][2],a[ky][mt][3], b[6],b[7]);
                    }
                }
            }
        }
    }
}

// Fused BasicBlock per (b,slot). 8 warps = 2cv x 2wm x 2wn, 29 iters.
// it<28:  cv0 conv1 rows (y,y+1);  cv1 conv2 rows (y-4,y-3) for it>=2.
// it==28: BOTH run conv2 tail (cv0 rows 54-55, cv1 rows 52-53).
__global__ void __launch_bounds__(256,1) fused_block(
    const float* __restrict__ x,
    const float* __restrict__ w1_all, const float* __restrict__ bn1_s, const float* __restrict__ bn1_b,
    const float* __restrict__ w2_all, const float* __restrict__ bn2_s, const float* __restrict__ bn2_b,
    float* __restrict__ out)
{
    extern __shared__ char smem[];
    const int tid = threadIdx.x, wid = tid>>5, lane = tid&31;
    const int cv = wid>>2;
    const int wm = (wid>>1)&1;
    const int wn = (wid&1)^cv;
    const int bs = blockIdx.x, b = bs>>1;
    const int e = g_eidx[bs];
    const float wt = g_ewt[bs];
    const float* in = x + (size_t)b*CHW;
    float* dst = out + (size_t)b*CHW;
    const uint32_t sbase = smem_u32(smem);

    for (int i=tid; i<(SM_TOTAL-SM_XR)/4; i+=256) ((uint32_t*)(smem+SM_XR))[i] = 0;

    for (int p=tid; p<4096; p+=256){
        int co = p>>6, ci = p&63;
        const float* wp1 = w1_all + (size_t)e*NC*NC*9 + (size_t)p*9;
        const float* wp2 = w2_all + (size_t)e*NC*NC*9 + (size_t)p*9;
        uint32_t off0 = (uint32_t)co*128 + (((uint32_t)(ci*2)) ^ ((uint32_t)(co&7)<<4));
        #pragma unroll
        for (int g9=0; g9<9; g9++){
            *(__half*)(smem + SM_W1 + g9*WT + off0) = __float2half(wp1[g9]);
            *(__half*)(smem + SM_W2 + g9*WT + off0) = __float2half(wp2[g9]);
        }
    }
    __syncthreads();
    {
        __half t[14];
        #pragma unroll
        for (int r=0;r<3;r++){ loadx_regs(in, r, t, tid); stsx_regs(smem, r, t, tid); }
    }

    // both bn sets (needed for the iter-28 role swap)
    const int g = lane>>2;
    float s1a[2], b1a[2], s1b[2], b1b[2], s2a[2], b2a[2], s2b[2], b2b[2];
    #pragma unroll
    for (int mt=0; mt<2; mt++){
        int co0 = wm*32 + mt*16 + g;
        s1a[mt]=bn1_s[e*NC+co0];   b1a[mt]=bn1_b[e*NC+co0];
        s1b[mt]=bn1_s[e*NC+co0+8]; b1b[mt]=bn1_b[e*NC+co0+8];
        s2a[mt]=bn2_s[e*NC+co0];   b2a[mt]=bn2_b[e*NC+co0];
        s2b[mt]=bn2_s[e*NC+co0+8]; b2b[mt]=bn2_b[e*NC+co0+8];
    }
    __syncthreads();

    const int sub = lane>>3, r = lane&7;
    uint32_t rAoff[2], sxA[2];
    #pragma unroll
    for (int mt=0; mt<2; mt++){
        uint32_t rowA = (uint32_t)(wm*32 + mt*16 + (sub&1)*8 + r);
        rAoff[mt] = rowA*128;
        sxA[mt]   = (rowA&7)<<4;
    }
    const uint32_t kbA0 = (uint32_t)((sub>>1)*16);
    const uint32_t rb0  = (uint32_t)(wn*32 + (sub>>1)*8 + r);
    const uint32_t kbB0 = (uint32_t)((sub&1)*16);
    const int xq = 2*(lane&3);

    __half hb0[14], hb1[14];
    loadx_regs(in, 3, hb0, tid);
    loadx_regs(in, 4, hb1, tid);

    for (int it=0; it<29; it++){
        const int y = 2*it;
        if (it>0){
            stsx_regs(smem, y+1, hb0, tid);
            stsx_regs(smem, y+2, hb1, tid);
            __syncthreads();
            loadx_regs(in, y+3, hb0, tid);
            loadx_regs(in, y+4, hb1, tid);
        }
        const int role = (it==28) ? 1 : cv;               // 0=conv1, 1=conv2
        const bool act = (it==28) ? true : (cv==0 ? true : (it>=2));
        if (act){
            const int r0 = (it==28) ? (cv==0 ? 54 : 52) : (role==0 ? y : y-4);
            uint32_t dyb[4], vmask = 0;
            #pragma unroll
            for (int d=0; d<4; d++){
                int iy = r0 + d - 1;
                if (iy >= 0 && iy < NH) vmask |= 1u<<d;
                int ic = iy < 0 ? 0 : iy;
                dyb[d] = role==0 ? sbase + SM_XR + (uint32_t)(ic&3)*SLOT
                                 : sbase + SM_YR + (uint32_t)(ic%7)*SLOT;
            }
            float C[2][2][4][4];
            #pragma unroll
            for (int rr=0;rr<2;rr++)
                #pragma unroll
                for (int mt=0;mt<2;mt++)
                    #pragma unroll
                    for (int t=0;t<4;t++){ C[rr][mt][t][0]=0;C[rr][mt][t][1]=0;C[rr][mt][t][2]=0;C[rr][mt][t][3]=0; }

            const uint32_t wOff = role ? SM_W2 : SM_W1;
            if (wn==0) conv_pair<0>(sbase,wOff,dyb,vmask,rAoff,sxA,kbA0,rb0,kbB0,(uint32_t)lane,C);
            else       conv_pair<1>(sbase,wOff,dyb,vmask,rAoff,sxA,kbA0,rb0,kbB0,(uint32_t)lane,C);

            if (role==0){
                #pragma unroll
                for (int rr=0;rr<2;rr++){
                    int yr = r0+rr;
                    char* yb = smem + SM_YR + (uint32_t)(yr%7)*SLOT;
                    #pragma unroll
                    for (int mt=0;mt<2;mt++){
                        int co0 = wm*32 + mt*16 + g, co1 = co0+8;
                        #pragma unroll
                        for (int t=0;t<4;t++){
                            if (wn==1 && t==3) continue;
                            int px = wn*32 + t*8 + xq;
                            float v0 = fmaxf(C[rr][mt][t][0]*s1a[mt] + b1a[mt], 0.f);
                            float v1 = fmaxf(C[rr][mt][t][1]*s1a[mt] + b1a[mt], 0.f);
                            float v2 = fmaxf(C[rr][mt][t][2]*s1b[mt] + b1b[mt], 0.f);
                            float v3 = fmaxf(C[rr][mt][t][3]*s1b[mt] + b1b[mt], 0.f);
                            uint32_t c0 = (uint32_t)(px+1), c1 = (uint32_t)(px+2);
                            uint32_t s0 = (c0&7)<<4, s1 = (c1&7)<<4;
                            *(__half*)(yb + c0*128 + (((uint32_t)(co0*2)) ^ s0)) = __float2half(v0);
                            *(__half*)(yb + c1*128 + (((uint32_t)(co0*2)) ^ s1)) = __float2half(v1);
                            *(__half*)(yb + c0*128 + (((uint32_t)(co1*2)) ^ s0)) = __float2half(v2);
                            *(__half*)(yb + c1*128 + (((uint32_t)(co1*2)) ^ s1)) = __float2half(v3);
                        }
                    }
                }
            } else {
                #pragma unroll
                for (int rr=0;rr<2;rr++){
                    int yr = r0+rr;
                    #pragma unroll
                    for (int mt=0;mt<2;mt++){
                        int co0 = wm*32 + mt*16 + g, co1 = co0+8;
                        #pragma unroll
                        for (int t=0;t<4;t++){
                            if (wn==1 && t==3) continue;
                            int px = wn*32 + t*8 + xq;
                            float v0 = C[rr][mt][t][0]*s2a[mt] + b2a[mt];
                            float v1 = C[rr][mt][t][1]*s2a[mt] + b2a[mt];
                            float v2 = C[rr][mt][t][2]*s2b[mt] + b2b[mt];
                            float v3 = C[rr][mt][t][3]*s2b[mt] + b2b[mt];
                            int i0 = co0*HW + yr*NW + px;
                            int i1 = co1*HW + yr*NW + px;
                            float2 r0v = *(const float2*)(in+i0);
                            float2 r1v = *(const float2*)(in+i1);
                            atomicAdd(dst+i0,   wt*fmaxf(v0+r0v.x,0.f));
                            atomicAdd(dst+i0+1, wt*fmaxf(v1+r0v.y,0.f));
                            atomicAdd(dst+i1,   wt*fmaxf(v2+r1v.x,0.f));
                            atomicAdd(dst+i1+1, wt*fmaxf(v3+r1v.y,0.f));
                        }
                    }
                }
            }
        }
        __syncthreads();
    }
}

extern "C" void kernel_launch(void* const* d_in, const int* in_sizes, int n_in,
                              void* d_out, int out_size)
{
    const float* x       = (const float*)d_in[0];
    const float* gate_w  = (const float*)d_in[1];
    const float* gate_b  = (const float*)d_in[2];
    const float* conv1_w = (const float*)d_in[3];
    const float* bn1_s   = (const float*)d_in[4];
    const float* bn1_b   = (const float*)d_in[5];
    const float* conv2_w = (const float*)d_in[6];
    const float* bn2_s   = (const float*)d_in[7];
    const float* bn2_b   = (const float*)d_in[8];
    float* out = (float*)d_out;

    pool_zero_gate<<<dim3(NB,12), 256>>>(x, gate_w, gate_b, out, out_size);

    cudaFuncSetAttribute(fused_block, cudaFuncAttributeMaxDynamicSharedMemorySize, SM_TOTAL);
    fused_block<<<128, 256, SM_TOTAL>>>(x, conv1_w, bn1_s, bn1_b,
                                        conv2_w, bn2_s, bn2_b, out);
}

// round 16
// speedup vs baseline: 1.3242x; 1.0080x over previous
#include <cuda_runtime.h>
#include <cuda_fp16.h>
#include <math.h>
#include <stdint.h>

#define NB 64
#define NC 64
#define NH 56
#define NW 56
#define HW 3136
#define CHW 200704
#define OUT_MAIN (NB*CHW)

__device__ int   g_eidx[NB*2];
__device__ float g_ewt[NB*2];
__device__ float g_pooled[NB*NC];
__device__ unsigned int g_pcount;

#define WT      8192
#define SM_W1   0
#define SM_W2   73728
#define SLOT    7424                 // 58 rows x 128B
#define SM_XR   147456               // 4 slots
#define SM_YR   177152               // 7 slots
#define SM_TOTAL 229120

__device__ __forceinline__ uint32_t smem_u32(const void* p){
    uint32_t a; asm("{ .reg .u64 t; cvta.to.shared.u64 t, %1; cvt.u32.u64 %0, t; }":"=r"(a):"l"(p)); return a;
}
#define LDSM4(d0,d1,d2,d3,a) \
    asm volatile("ldmatrix.sync.aligned.m8n8.x4.shared.b16 {%0,%1,%2,%3},[%4];" \
        : "=r"(d0),"=r"(d1),"=r"(d2),"=r"(d3) : "r"(a))
#define LDSM2(d0,d1,a) \
    asm volatile("ldmatrix.sync.aligned.m8n8.x2.shared.b16 {%0,%1},[%2];" \
        : "=r"(d0),"=r"(d1) : "r"(a))
#define MMA16816(C,a0,a1,a2,a3,b0,b1) \
    asm volatile("mma.sync.aligned.m16n8k16.row.col.f32.f16.f16.f32 " \
        "{%0,%1,%2,%3},{%4,%5,%6,%7},{%8,%9},{%0,%1,%2,%3};" \
        : "+f"((C)[0]),"+f"((C)[1]),"+f"((C)[2]),"+f"((C)[3]) \
        : "r"(a0),"r"(a1),"r"(a2),"r"(a3),"r"(b0),"r"(b1))

// ---------------------------------------------------------------------------
// One launch: pooling blocks (gg<8), streaming-zero blocks (gg>=8, __stwt so
// L2 stays clean for the fused kernel), gate in the last-arriving block.
// ---------------------------------------------------------------------------
__global__ void pool_zero_gate(const float* __restrict__ x, const float* __restrict__ gw,
                               const float* __restrict__ gb, float* __restrict__ out,
                               int out_size){
    int b = blockIdx.x, gg = blockIdx.y;
    if (gg < 8){
        int w = threadIdx.x>>5, l = threadIdx.x&31;
        int c = gg*8 + w;
        const float4* p = (const float4*)(x + ((size_t)b*NC + c)*HW);
        float s = 0.f;
        for (int i=l; i<HW/4; i+=32){ float4 v = p[i]; s += (v.x+v.y)+(v.z+v.w); }
        #pragma unroll
        for (int o=16;o>0;o>>=1) s += __shfl_xor_sync(0xffffffffu, s, o);
        if (l==0) g_pooled[b*NC+c] = s * (1.0f/(float)HW);
    } else {
        // zero main output region with streaming stores (no dirty L2 lines)
        int zi = (gg-8)*NB + b;                   // 0..255
        float4 z4 = make_float4(0.f,0.f,0.f,0.f);
        float4* zp = (float4*)out + (size_t)zi*(OUT_MAIN/4/256);
        #pragma unroll 7
        for (int i=(int)threadIdx.x; i<OUT_MAIN/4/256; i+=256) __stwt(&zp[i], z4);
        if (zi==0){   // tail (dense_w region etc.)
            for (int i=OUT_MAIN+(int)threadIdx.x; i<out_size; i+=256) __stwt(&out[i], 0.f);
        }
    }
    __threadfence();
    __shared__ int last;
    if (threadIdx.x==0){
        unsigned old = atomicAdd(&g_pcount, 1u);
        last = (((old+1u) % 768u)==0u);
    }
    __syncthreads();
    if (last && threadIdx.x < NB){
        int bb = threadIdx.x;
        float lg[8];
        #pragma unroll
        for (int e=0;e<8;e++){
            float t = gb[e];
            for (int cc=0;cc<NC;cc++) t += g_pooled[bb*NC+cc]*gw[e*NC+cc];
            lg[e] = t;
        }
        int i0=0; float v0=lg[0];
        #pragma unroll
        for (int e=1;e<8;e++) if (lg[e]>v0){ v0=lg[e]; i0=e; }
        int i1=-1; float v1=-1e30f;
        #pragma unroll
        for (int e=0;e<8;e++){ if (e==i0) continue; if (lg[e]>v1){ v1=lg[e]; i1=e; } }
        float w0 = 1.0f/(1.0f+expf(v1-v0));
        g_eidx[bb*2+0]=i0; g_eidx[bb*2+1]=i1;
        g_ewt [bb*2+0]=w0; g_ewt [bb*2+1]=1.0f-w0;
        if (out_size >= OUT_MAIN + NB*8){
            out[OUT_MAIN + bb*8 + i0] = w0;
            out[OUT_MAIN + bb*8 + i1] = 1.0f-w0;
        }
    }
}

__device__ __forceinline__ void loadx_regs(const float* __restrict__ in, int r,
                                           __half* hb, int tid){
    if (r >= NH) return;
    int ci = tid>>2, q = tid&3;
    const float* src = in + (size_t)ci*HW + r*NW + q*14;
    #pragma unroll
    for (int j=0;j<14;j++) hb[j] = __float2half(src[j]);
}
__device__ __forceinline__ void stsx_regs(char* smem, int r, const __half* hb, int tid){
    if (r >= NH) return;
    int ci = tid>>2, q = tid&3;
    uint32_t base = SM_XR + (uint32_t)(r&3)*SLOT;
    uint32_t cb2 = (uint32_t)(ci*2);
    #pragma unroll
    for (int j=0;j<14;j++){
        uint32_t c = (uint32_t)(q*14 + j + 1);
        *(__half*)(smem + base + c*128 + (cb2 ^ ((c&7)<<4))) = hb[j];
    }
}

// Warp computes M32xN32 for TWO adjacent rows; A frags shared, B rows shared.
template<int WN>
__device__ __forceinline__ void conv_pair(
    uint32_t sbase, uint32_t wOff, const uint32_t dyb[4], uint32_t vmask,
    const uint32_t rAoff[2], const uint32_t sxA[2], uint32_t kbA0,
    uint32_t rb0, uint32_t kbB0, uint32_t lane, float (&C)[2][2][4][4])
{
    #pragma unroll 1
    for (int kx=0; kx<3; kx++){
        #pragma unroll
        for (int ks=0; ks<4; ks++){
            uint32_t kA = kbA0 + (uint32_t)ks*32;
            uint32_t kB = kbB0 + (uint32_t)ks*32;
            uint32_t a[3][2][4];
            #pragma unroll
            for (int ky=0; ky<3; ky++){
                uint32_t aT = sbase + wOff + (uint32_t)(3*ky+kx)*WT;
                #pragma unroll
                for (int mt=0; mt<2; mt++)
                    LDSM4(a[ky][mt][0],a[ky][mt][1],a[ky][mt][2],a[ky][mt][3],
                          aT + rAoff[mt] + (kA ^ sxA[mt]));
            }
            #pragma unroll
            for (int d=0; d<4; d++){
                if (!((vmask>>d)&1u)) continue;
                uint32_t b[8];
                uint32_t rb = rb0 + (uint32_t)kx;
                LDSM4(b[0],b[1],b[2],b[3], dyb[d] + rb*128 + (kB ^ ((rb&7)<<4)));
                if (WN==0){
                    uint32_t rb2 = rb + 16;
                    LDSM4(b[4],b[5],b[6],b[7], dyb[d] + rb2*128 + (kB ^ ((rb2&7)<<4)));
                } else {
                    uint32_t rb2 = 48u + (lane&7) + (uint32_t)kx;
                    uint32_t kk = (uint32_t)ks*32 + ((lane>>3)&1u)*16u;
                    LDSM2(b[4],b[5], dyb[d] + rb2*128 + (kk ^ ((rb2&7)<<4)));
                }
                #pragma unroll
                for (int rr=0; rr<2; rr++){
                    int ky = d - rr;
                    if (ky < 0 || ky > 2) continue;
                    #pragma unroll
                    for (int mt=0; mt<2; mt++){
                        MMA16816(C[rr][mt][0], a[ky][mt][0],a[ky][mt][1],a[ky][mt][2],a[ky][mt][3], b[0],b[1]);
                        MMA16816(C[rr][mt][1], a[ky][mt][0],a[ky][mt][1],a[ky][mt][2],a[ky][mt][3], b[2],b[3]);
                        MMA16816(C[rr][mt][2], a[ky][mt][0],a[ky][mt][1],a[ky][mt][2],a[ky][mt][3], b[4],b[5]);
                        if (WN==0)
                        MMA16816(C[rr][mt][3], a[ky][mt][0],a[ky][mt][1],a[ky][mt][2],a[ky][mt][3], b[6],b[7]);
                    }
                }
            }
        }
    }
}

// Fused BasicBlock per (b,slot). 8 warps = 2cv x 2wm x 2wn, 29 iters.
// it<28:  cv0 conv1 rows (y,y+1);  cv1 conv2 rows (y-4,y-3) for it>=2.
// it==28: BOTH run conv2 tail (cv0 rows 54-55, cv1 rows 52-53).
__global__ void __launch_bounds__(256,1) fused_block(
    const float* __restrict__ x,
    const float* __restrict__ w1_all, const float* __restrict__ bn1_s, const float* __restrict__ bn1_b,
    const float* __restrict__ w2_all, const float* __restrict__ bn2_s, const float* __restrict__ bn2_b,
    float* __restrict__ out)
{
    extern __shared__ char smem[];
    const int tid = threadIdx.x, wid = tid>>5, lane = tid&31;
    const int cv = wid>>2;
    const int wm = (wid>>1)&1;
    const int wn = (wid&1)^cv;
    const int bs = blockIdx.x, b = bs>>1;
    const int e = g_eidx[bs];
    const float wt = g_ewt[bs];
    const float* in = x + (size_t)b*CHW;
    float* dst = out + (size_t)b*CHW;
    const uint32_t sbase = smem_u32(smem);

    for (int i=tid; i<(SM_TOTAL-SM_XR)/4; i+=256) ((uint32_t*)(smem+SM_XR))[i] = 0;

    for (int p=tid; p<4096; p+=256){
        int co = p>>6, ci = p&63;
        const float* wp1 = w1_all + (size_t)e*NC*NC*9 + (size_t)p*9;
        const float* wp2 = w2_all + (size_t)e*NC*NC*9 + (size_t)p*9;
        uint32_t off0 = (uint32_t)co*128 + (((uint32_t)(ci*2)) ^ ((uint32_t)(co&7)<<4));
        #pragma unroll
        for (int g9=0; g9<9; g9++){
            *(__half*)(smem + SM_W1 + g9*WT + off0) = __float2half(wp1[g9]);
            *(__half*)(smem + SM_W2 + g9*WT + off0) = __float2half(wp2[g9]);
        }
    }
    __syncthreads();
    {
        __half t[14];
        #pragma unroll
        for (int r=0;r<3;r++){ loadx_regs(in, r, t, tid); stsx_regs(smem, r, t, tid); }
    }

    // both bn sets (needed for the iter-28 role swap)
    const int g = lane>>2;
    float s1a[2], b1a[2], s1b[2], b1b[2], s2a[2], b2a[2], s2b[2], b2b[2];
    #pragma unroll
    for (int mt=0; mt<2; mt++){
        int co0 = wm*32 + mt*16 + g;
        s1a[mt]=bn1_s[e*NC+co0];   b1a[mt]=bn1_b[e*NC+co0];
        s1b[mt]=bn1_s[e*NC+co0+8]; b1b[mt]=bn1_b[e*NC+co0+8];
        s2a[mt]=bn2_s[e*NC+co0];   b2a[mt]=bn2_b[e*NC+co0];
        s2b[mt]=bn2_s[e*NC+co0+8]; b2b[mt]=bn2_b[e*NC+co0+8];
    }
    __syncthreads();

    const int sub = lane>>3, r = lane&7;
    uint32_t rAoff[2], sxA[2];
    #pragma unroll
    for (int mt=0; mt<2; mt++){
        uint32_t rowA = (uint32_t)(wm*32 + mt*16 + (sub&1)*8 + r);
        rAoff[mt] = rowA*128;
        sxA[mt]   = (rowA&7)<<4;
    }
    const uint32_t kbA0 = (uint32_t)((sub>>1)*16);
    const uint32_t rb0  = (uint32_t)(wn*32 + (sub>>1)*8 + r);
    const uint32_t kbB0 = (uint32_t)((sub&1)*16);
    const int xq = 2*(lane&3);

    __half hb0[14], hb1[14];
    loadx_regs(in, 3, hb0, tid);
    loadx_regs(in, 4, hb1, tid);

    for (int it=0; it<29; it++){
        const int y = 2*it;
        if (it>0){
            stsx_regs(smem, y+1, hb0, tid);
            stsx_regs(smem, y+2, hb1, tid);
            __syncthreads();
            loadx_regs(in, y+3, hb0, tid);
            loadx_regs(in, y+4, hb1, tid);
        }
        const int role = (it==28) ? 1 : cv;               // 0=conv1, 1=conv2
        const bool act = (it==28) ? true : (cv==0 ? true : (it>=2));
        if (act){
            const int r0 = (it==28) ? (cv==0 ? 54 : 52) : (role==0 ? y : y-4);
            uint32_t dyb[4], vmask = 0;
            #pragma unroll
            for (int d=0; d<4; d++){
                int iy = r0 + d - 1;
                if (iy >= 0 && iy < NH) vmask |= 1u<<d;
                int ic = iy < 0 ? 0 : iy;
                dyb[d] = role==0 ? sbase + SM_XR + (uint32_t)(ic&3)*SLOT
                                 : sbase + SM_YR + (uint32_t)(ic%7)*SLOT;
            }
            float C[2][2][4][4];
            #pragma unroll
            for (int rr=0;rr<2;rr++)
                #pragma unroll
                for (int mt=0;mt<2;mt++)
                    #pragma unroll
                    for (int t=0;t<4;t++){ C[rr][mt][t][0]=0;C[rr][mt][t][1]=0;C[rr][mt][t][2]=0;C[rr][mt][t][3]=0; }

            const uint32_t wOff = role ? SM_W2 : SM_W1;
            if (wn==0) conv_pair<0>(sbase,wOff,dyb,vmask,rAoff,sxA,kbA0,rb0,kbB0,(uint32_t)lane,C);
            else       conv_pair<1>(sbase,wOff,dyb,vmask,rAoff,sxA,kbA0,rb0,kbB0,(uint32_t)lane,C);

            if (role==0){
                #pragma unroll
                for (int rr=0;rr<2;rr++){
                    int yr = r0+rr;
                    char* yb = smem + SM_YR + (uint32_t)(yr%7)*SLOT;
                    #pragma unroll
                    for (int mt=0;mt<2;mt++){
                        int co0 = wm*32 + mt*16 + g, co1 = co0+8;
                        #pragma unroll
                        for (int t=0;t<4;t++){
                            if (wn==1 && t==3) continue;
                            int px = wn*32 + t*8 + xq;
                            float v0 = fmaxf(C[rr][mt][t][0]*s1a[mt] + b1a[mt], 0.f);
                            float v1 = fmaxf(C[rr][mt][t][1]*s1a[mt] + b1a[mt], 0.f);
                            float v2 = fmaxf(C[rr][mt][t][2]*s1b[mt] + b1b[mt], 0.f);
                            float v3 = fmaxf(C[rr][mt][t][3]*s1b[mt] + b1b[mt], 0.f);
                            uint32_t c0 = (uint32_t)(px+1), c1 = (uint32_t)(px+2);
                            uint32_t s0 = (c0&7)<<4, s1 = (c1&7)<<4;
                            *(__half*)(yb + c0*128 + (((uint32_t)(co0*2)) ^ s0)) = __float2half(v0);
                            *(__half*)(yb + c1*128 + (((uint32_t)(co0*2)) ^ s1)) = __float2half(v1);
                            *(__half*)(yb + c0*128 + (((uint32_t)(co1*2)) ^ s0)) = __float2half(v2);
                            *(__half*)(yb + c1*128 + (((uint32_t)(co1*2)) ^ s1)) = __float2half(v3);
                        }
                    }
                }
            } else {
                #pragma unroll
                for (int rr=0;rr<2;rr++){
                    int yr = r0+rr;
                    #pragma unroll
                    for (int mt=0;mt<2;mt++){
                        int co0 = wm*32 + mt*16 + g, co1 = co0+8;
                        #pragma unroll
                        for (int t=0;t<4;t++){
                            if (wn==1 && t==3) continue;
                            int px = wn*32 + t*8 + xq;
                            float v0 = C[rr][mt][t][0]*s2a[mt] + b2a[mt];
                            float v1 = C[rr][mt][t][1]*s2a[mt] + b2a[mt];
                            float v2 = C[rr][mt][t][2]*s2b[mt] + b2b[mt];
                            float v3 = C[rr][mt][t][3]*s2b[mt] + b2b[mt];
                            int i0 = co0*HW + yr*NW + px;
                            int i1 = co1*HW + yr*NW + px;
                            float2 r0v = *(const float2*)(in+i0);
                            float2 r1v = *(const float2*)(in+i1);
                            atomicAdd(dst+i0,   wt*fmaxf(v0+r0v.x,0.f));
                            atomicAdd(dst+i0+1, wt*fmaxf(v1+r0v.y,0.f));
                            atomicAdd(dst+i1,   wt*fmaxf(v2+r1v.x,0.f));
                            atomicAdd(dst+i1+1, wt*fmaxf(v3+r1v.y,0.f));
                        }
                    }
                }
            }
        }
        __syncthreads();
    }
}

extern "C" void kernel_launch(void* const* d_in, const int* in_sizes, int n_in,
                              void* d_out, int out_size)
{
    const float* x       = (const float*)d_in[0];
    const float* gate_w  = (const float*)d_in[1];
    const float* gate_b  = (const float*)d_in[2];
    const float* conv1_w = (const float*)d_in[3];
    const float* bn1_s   = (const float*)d_in[4];
    const float* bn1_b   = (const float*)d_in[5];
    const float* conv2_w = (const float*)d_in[6];
    const float* bn2_s   = (const float*)d_in[7];
    const float* bn2_b   = (const float*)d_in[8];
    float* out = (float*)d_out;

    pool_zero_gate<<<dim3(NB,12), 256>>>(x, gate_w, gate_b, out, out_size);

    cudaFuncSetAttribute(fused_block, cudaFuncAttributeMaxDynamicSharedMemorySize, SM_TOTAL);
    fused_block<<<128, 256, SM_TOTAL>>>(x, conv1_w, bn1_s, bn1_b,
                                        conv2_w, bn2_s, bn2_b, out);
}